// round 7
// baseline (speedup 1.0000x reference)
#include <cuda_runtime.h>
#include <cuda_bf16.h>
#include <cstdint>

#define NN 100000
#define NE 800000
#define F  128
#define C  64

typedef unsigned long long ull;

// ---- device scratch (no allocations allowed) ----
__device__ float4 g_y4[NN * (C / 4)];   // projected features y = x @ W^T (25.6 MB, L2-resident)
__device__ int    g_cnt[NN];            // degree histogram (zeroed at end of k_out)
__device__ int    g_off[NN];            // exclusive offsets; post-scatter = inclusive
__device__ int    g_srcs[NE];           // CSR-by-dst neighbor lists

// ---------------- degree histogram (int4: 4 edges/thread) ----------------
__global__ void k_count(const int4* __restrict__ dst4) {
    int e4 = blockIdx.x * 256 + threadIdx.x;
    if (e4 < NE / 4) {
        int4 d = dst4[e4];
        atomicAdd(&g_cnt[d.x], 1);
        atomicAdd(&g_cnt[d.y], 1);
        atomicAdd(&g_cnt[d.z], 1);
        atomicAdd(&g_cnt[d.w], 1);
    }
}

// ---------------- full exclusive scan in ONE block ----------------
// 1024 threads, each owns a contiguous chunk of 25 int4 (100 ints).
#define CH 25          // int4 per thread
#define NQ (NN / 4)    // 25000 int4 total
__global__ void __launch_bounds__(1024) k_scan() {
    __shared__ int ws[32];
    int t = threadIdx.x;
    int lane = t & 31, wid = t >> 5;
    const int4* cnt4 = (const int4*)g_cnt;
    int beg = t * CH;
    int end = beg + CH < NQ ? beg + CH : NQ;

    // pass 1: chunk sum
    int s = 0;
    for (int i = beg; i < end; i++) {
        int4 v = cnt4[i];
        s += v.x + v.y + v.z + v.w;
    }
    // block scan of 1024 chunk sums
    int incl = s;
    #pragma unroll
    for (int o = 1; o < 32; o <<= 1) {
        int u = __shfl_up_sync(~0u, incl, o);
        if (lane >= o) incl += u;
    }
    if (lane == 31) ws[wid] = incl;
    __syncthreads();
    if (t < 32) {
        int w0 = ws[t];
        int wi = w0;
        #pragma unroll
        for (int o = 1; o < 32; o <<= 1) {
            int u = __shfl_up_sync(~0u, wi, o);
            if (t >= o) wi += u;
        }
        ws[t] = wi - w0;   // exclusive warp offset
    }
    __syncthreads();
    int run = (incl - s) + ws[wid];   // thread-exclusive prefix

    // pass 2: write exclusive offsets
    int4* off4 = (int4*)g_off;
    for (int i = beg; i < end; i++) {
        int4 v = cnt4[i];
        int4 o;
        o.x = run;
        o.y = run + v.x;
        o.z = o.y + v.y;
        o.w = o.z + v.z;
        run = o.w + v.w;
        off4[i] = o;
    }
}

// ---------------- scatter edges (cursor-free: bumps g_off itself) ----------------
__global__ void k_scatter(const int4* __restrict__ src4,
                          const int4* __restrict__ dst4) {
    int e4 = blockIdx.x * 256 + threadIdx.x;
    if (e4 < NE / 4) {
        int4 d = dst4[e4];
        int4 s = src4[e4];
        g_srcs[atomicAdd(&g_off[d.x], 1)] = s.x;
        g_srcs[atomicAdd(&g_off[d.y], 1)] = s.y;
        g_srcs[atomicAdd(&g_off[d.z], 1)] = s.z;
        g_srcs[atomicAdd(&g_off[d.w], 1)] = s.w;
    }
}

// ============ tensor-core projection via mma.sync (HMMA, plain PTX ISA) ============
// Per CTA: M=128 nodes (8 warps x 16 rows), N=64 classes, K=128.
// bf16 2-term split: D = Ahi*Bhi + Alo*Bhi + Ahi*Blo  (fp32 accumulate).
#define AS 136
#define ASB (AS * 2)
#define SM_A_HI 0
#define SM_A_LO (128 * ASB)
#define SM_B_HI (2 * 128 * ASB)
#define SM_B_LO (2 * 128 * ASB + 64 * ASB)
#define SM_TOTAL (2 * 128 * ASB + 2 * 64 * ASB)   // 104448

__device__ __forceinline__ uint32_t pack_bf2(__nv_bfloat16 a, __nv_bfloat16 b) {
    return (uint32_t)__bfloat16_as_ushort(a) | ((uint32_t)__bfloat16_as_ushort(b) << 16);
}

__device__ __forceinline__ void mma16816(float* c, const uint32_t* a,
                                         uint32_t b0, uint32_t b1) {
    asm volatile(
        "mma.sync.aligned.m16n8k16.row.col.f32.bf16.bf16.f32 "
        "{%0,%1,%2,%3}, {%4,%5,%6,%7}, {%8,%9}, {%0,%1,%2,%3};"
        : "+f"(c[0]), "+f"(c[1]), "+f"(c[2]), "+f"(c[3])
        : "r"(a[0]), "r"(a[1]), "r"(a[2]), "r"(a[3]), "r"(b0), "r"(b1));
}

__global__ void __launch_bounds__(256, 2) k_gemm_mma(const float* __restrict__ x,
                                                     const float* __restrict__ W) {
    extern __shared__ char smem[];
    int tid = threadIdx.x;
    int base = blockIdx.x * 128;

    for (int i = tid; i < 128 * 32; i += 256) {
        int row = i >> 5, kq = i & 31;
        int gn = base + row;
        float4 v = make_float4(0.f, 0.f, 0.f, 0.f);
        if (gn < NN) v = ((const float4*)x)[(size_t)gn * 32 + kq];
        float e[4] = {v.x, v.y, v.z, v.w};
        __nv_bfloat16 h[4], l[4];
        #pragma unroll
        for (int j = 0; j < 4; j++) {
            h[j] = __float2bfloat16(e[j]);
            l[j] = __float2bfloat16(e[j] - __bfloat162float(h[j]));
        }
        uint32_t off = row * ASB + kq * 8;
        *(ull*)(smem + SM_A_HI + off) =
            (ull)pack_bf2(h[0], h[1]) | ((ull)pack_bf2(h[2], h[3]) << 32);
        *(ull*)(smem + SM_A_LO + off) =
            (ull)pack_bf2(l[0], l[1]) | ((ull)pack_bf2(l[2], l[3]) << 32);
    }
    for (int i = tid; i < 64 * 32; i += 256) {
        int row = i >> 5, kq = i & 31;
        float4 v = ((const float4*)W)[row * 32 + kq];
        float e[4] = {v.x, v.y, v.z, v.w};
        __nv_bfloat16 h[4], l[4];
        #pragma unroll
        for (int j = 0; j < 4; j++) {
            h[j] = __float2bfloat16(e[j]);
            l[j] = __float2bfloat16(e[j] - __bfloat162float(h[j]));
        }
        uint32_t off = row * ASB + kq * 8;
        *(ull*)(smem + SM_B_HI + off) =
            (ull)pack_bf2(h[0], h[1]) | ((ull)pack_bf2(h[2], h[3]) << 32);
        *(ull*)(smem + SM_B_LO + off) =
            (ull)pack_bf2(l[0], l[1]) | ((ull)pack_bf2(l[2], l[3]) << 32);
    }
    __syncthreads();

    int w  = tid >> 5;
    int l  = tid & 31;
    int g  = l >> 2;
    int tg = l & 3;
    int ar0 = w * 16 + g;

    float c[8][4];
    #pragma unroll
    for (int nt = 0; nt < 8; nt++)
        #pragma unroll
        for (int j = 0; j < 4; j++) c[nt][j] = 0.f;

    #pragma unroll
    for (int ks = 0; ks < 8; ks++) {
        int k0 = ks * 16;
        uint32_t aoff = ar0 * ASB + (k0 + tg * 2) * 2;
        uint32_t ah[4], al[4];
        ah[0] = *(const uint32_t*)(smem + SM_A_HI + aoff);
        ah[1] = *(const uint32_t*)(smem + SM_A_HI + aoff + 8 * ASB);
        ah[2] = *(const uint32_t*)(smem + SM_A_HI + aoff + 16);
        ah[3] = *(const uint32_t*)(smem + SM_A_HI + aoff + 8 * ASB + 16);
        al[0] = *(const uint32_t*)(smem + SM_A_LO + aoff);
        al[1] = *(const uint32_t*)(smem + SM_A_LO + aoff + 8 * ASB);
        al[2] = *(const uint32_t*)(smem + SM_A_LO + aoff + 16);
        al[3] = *(const uint32_t*)(smem + SM_A_LO + aoff + 8 * ASB + 16);
        #pragma unroll
        for (int nt = 0; nt < 8; nt++) {
            uint32_t boff = (nt * 8 + g) * ASB + (k0 + tg * 2) * 2;
            uint32_t bh0 = *(const uint32_t*)(smem + SM_B_HI + boff);
            uint32_t bh1 = *(const uint32_t*)(smem + SM_B_HI + boff + 16);
            uint32_t bl0 = *(const uint32_t*)(smem + SM_B_LO + boff);
            uint32_t bl1 = *(const uint32_t*)(smem + SM_B_LO + boff + 16);
            mma16816(c[nt], ah, bh0, bh1);
            mma16816(c[nt], al, bh0, bh1);
            mma16816(c[nt], ah, bl0, bl1);
        }
    }

    float2* yp = (float2*)g_y4;
    int gn0 = base + ar0;
    int gn1 = gn0 + 8;
    #pragma unroll
    for (int nt = 0; nt < 8; nt++) {
        if (gn0 < NN) yp[(size_t)gn0 * 32 + nt * 4 + tg] = make_float2(c[nt][0], c[nt][1]);
        if (gn1 < NN) yp[(size_t)gn1 * 32 + nt * 4 + tg] = make_float2(c[nt][2], c[nt][3]);
    }
}

// ---------------- gather + epilogue ----------------
// Post-scatter, g_off[v] = inclusive offset: jb = v?g_off[v-1]:0, je = g_off[v].
// Also re-zeroes g_cnt for the next graph replay (nothing reads it after k_scan).
__global__ void __launch_bounds__(256) k_out(const float* __restrict__ bn,
                                             float* __restrict__ out) {
    int tid = threadIdx.x;
    int gt = blockIdx.x * 256 + tid;
    if (gt < NN) g_cnt[gt] = 0;        // restore invariant for next replay

    int l  = tid & 15;
    int nl = tid >> 4;
    int v  = blockIdx.x * 16 + nl;     // 6250 * 16 == 100000

    float4 acc = g_y4[(size_t)v * 16 + l];   // self term

    int jb = v ? g_off[v - 1] : 0;
    int je = g_off[v];
    int j = jb;
    for (; j + 4 <= je; j += 4) {
        int s0 = g_srcs[j + 0];
        int s1 = g_srcs[j + 1];
        int s2 = g_srcs[j + 2];
        int s3 = g_srcs[j + 3];
        float4 t0 = g_y4[(size_t)s0 * 16 + l];
        float4 t1 = g_y4[(size_t)s1 * 16 + l];
        float4 t2 = g_y4[(size_t)s2 * 16 + l];
        float4 t3 = g_y4[(size_t)s3 * 16 + l];
        acc.x += t0.x + t1.x + t2.x + t3.x;
        acc.y += t0.y + t1.y + t2.y + t3.y;
        acc.z += t0.z + t1.z + t2.z + t3.z;
        acc.w += t0.w + t1.w + t2.w + t3.w;
    }
    for (; j < je; j++) {
        int s = g_srcs[j];
        float4 t = g_y4[(size_t)s * 16 + l];
        acc.x += t.x; acc.y += t.y; acc.z += t.z; acc.w += t.w;
    }

    float sc = 1.0f / (float)(je - jb + 1);
    float4 bb = ((const float4*)bn)[l];
    float4 o;
    o.x = acc.x * sc + bb.x;
    o.y = acc.y * sc + bb.y;
    o.z = acc.z * sc + bb.z;
    o.w = acc.w * sc + bb.w;
    ((float4*)out)[(size_t)v * 16 + l] = o;
}

extern "C" void kernel_launch(void* const* d_in, const int* in_sizes, int n_in,
                              void* d_out, int out_size) {
    const float* x    = (const float*)d_in[0];
    const int*   esrc = (const int*)d_in[1];
    const int*   edst = (const int*)d_in[2];
    const float* W    = (const float*)d_in[3];
    const float* bn   = (const float*)d_in[4];
    float* out = (float*)d_out;

    static cudaStream_t s1 = nullptr;
    static cudaEvent_t ev_root = nullptr, ev_gemm = nullptr;
    if (!s1) {
        cudaStreamCreateWithFlags(&s1, cudaStreamNonBlocking);
        cudaEventCreateWithFlags(&ev_root, cudaEventDisableTiming);
        cudaEventCreateWithFlags(&ev_gemm, cudaEventDisableTiming);
        cudaFuncSetAttribute(k_gemm_mma, cudaFuncAttributeMaxDynamicSharedMemorySize, SM_TOTAL);
    }

    // fork: GEMM on side stream, CSR build on main stream
    cudaEventRecord(ev_root, 0);
    cudaStreamWaitEvent(s1, ev_root, 0);
    k_gemm_mma<<<(NN + 127) / 128, 256, SM_TOTAL, s1>>>(x, W);
    cudaEventRecord(ev_gemm, s1);

    k_count<<<(NE / 4 + 255) / 256, 256>>>((const int4*)edst);
    k_scan<<<1, 1024>>>();
    k_scatter<<<(NE / 4 + 255) / 256, 256>>>((const int4*)esrc, (const int4*)edst);

    // join: k_out needs both g_y (gemm) and CSR
    cudaStreamWaitEvent(0, ev_gemm, 0);
    k_out<<<NN / 16, 256>>>(bn, out);
}

// round 8
// speedup vs baseline: 1.8567x; 1.8567x over previous
#include <cuda_runtime.h>
#include <cuda_bf16.h>
#include <cstdint>

#define NN 100000
#define NE 800000
#define F  128
#define C  64
#define NBLK 98                 // ceil(100000/1024)
#define VALMASK 0x3FFFFFFF
#define FLAG_A (1 << 30)
#define FLAG_P (2 << 30)

typedef unsigned long long ull;

// ---- device scratch (no allocations allowed) ----
__device__ float4 g_y4[NN * (C / 4)];   // projected features y = x @ W^T (25.6 MB, L2-resident)
__device__ int    g_cnt[NN];            // degree histogram (re-zeroed in k_out)
__device__ int    g_off[NN];            // exclusive offsets; post-scatter = inclusive
__device__ int    g_srcs[NE];           // CSR-by-dst neighbor lists
__device__ int    g_flags[NBLK];        // decoupled-lookback state (re-zeroed in k_out)

// ---------------- degree histogram (scalar, max TLP) ----------------
__global__ void k_count(const int* __restrict__ dst) {
    int e = blockIdx.x * 256 + threadIdx.x;
    if (e < NE) atomicAdd(&g_cnt[dst[e]], 1);
}

// ---------------- single-kernel exclusive scan (decoupled lookback) ----------------
// 98 blocks x 1024 threads, 1 element/thread (coalesced). All blocks co-resident.
__global__ void __launch_bounds__(1024) k_scan() {
    __shared__ int ws[32];
    __shared__ int s_pref;
    int b = blockIdx.x, t = threadIdx.x;
    int lane = t & 31, wid = t >> 5;
    int i = b * 1024 + t;
    int v = (i < NN) ? g_cnt[i] : 0;

    // block inclusive scan
    int incl = v;
    #pragma unroll
    for (int o = 1; o < 32; o <<= 1) {
        int u = __shfl_up_sync(~0u, incl, o);
        if (lane >= o) incl += u;
    }
    if (lane == 31) ws[wid] = incl;
    __syncthreads();
    if (t < 32) {
        int w0 = ws[t];
        int wi = w0;
        #pragma unroll
        for (int o = 1; o < 32; o <<= 1) {
            int u = __shfl_up_sync(~0u, wi, o);
            if (t >= o) wi += u;
        }
        ws[t] = wi - w0;   // exclusive warp offset
    }
    __syncthreads();
    int myincl = incl + ws[wid];

    // publish aggregate (block total = myincl of t==1023)
    if (t == 1023) {
        int agg = myincl & VALMASK;
        __threadfence();
        atomicExch(&g_flags[b], (b == 0 ? FLAG_P : FLAG_A) | agg);
    }

    // warp 0: lookback to compute this block's exclusive prefix
    if (wid == 0) {
        if (b == 0) {
            if (lane == 0) s_pref = 0;
        } else {
            int pref = 0;
            int w = b;                      // window covers [w-32, w)
            while (true) {
                int idx = w - 32 + lane;
                int f = (idx >= 0) ? atomicAdd(&g_flags[idx], 0) : (int)FLAG_P;
                unsigned st = ((unsigned)f) >> 30;   // 0 invalid, 1 agg, 2 prefix
                unsigned pm = __ballot_sync(~0u, st == 2u);
                unsigned vm = __ballot_sync(~0u, st >= 1u);
                if (pm) {
                    int hp = 31 - __clz(pm);         // highest lane holding a prefix
                    unsigned need = ~0u << hp;
                    if ((vm & need) == need) {
                        int contrib = (lane >= hp) ? (f & VALMASK) : 0;
                        #pragma unroll
                        for (int o = 16; o; o >>= 1)
                            contrib += __shfl_down_sync(~0u, contrib, o);
                        pref += __shfl_sync(~0u, contrib, 0);
                        break;
                    }
                } else if (vm == ~0u) {
                    int contrib = f & VALMASK;
                    #pragma unroll
                    for (int o = 16; o; o >>= 1)
                        contrib += __shfl_down_sync(~0u, contrib, o);
                    pref += __shfl_sync(~0u, contrib, 0);
                    w -= 32;
                }
                // else spin
            }
            if (lane == 0) s_pref = pref;
        }
    }
    __syncthreads();
    int pref = s_pref;

    // publish inclusive prefix for successors
    if (t == 1023 && b > 0) {
        __threadfence();
        atomicExch(&g_flags[b], FLAG_P | ((pref + myincl) & VALMASK));
    }

    if (i < NN) g_off[i] = pref + myincl - v;   // exclusive
}

// ---------------- scatter edges (cursor-free: bumps g_off itself) ----------------
__global__ void k_scatter(const int* __restrict__ src,
                          const int* __restrict__ dst) {
    int e = blockIdx.x * 256 + threadIdx.x;
    if (e < NE) {
        int d = dst[e];
        g_srcs[atomicAdd(&g_off[d], 1)] = src[e];
    }
}

// ============ tensor-core projection via mma.sync (HMMA, plain PTX ISA) ============
// Per CTA: M=128 nodes (8 warps x 16 rows), N=64 classes, K=128.
// bf16 2-term split: D = Ahi*Bhi + Alo*Bhi + Ahi*Blo  (fp32 accumulate).
#define AS 136
#define ASB (AS * 2)
#define SM_A_HI 0
#define SM_A_LO (128 * ASB)
#define SM_B_HI (2 * 128 * ASB)
#define SM_B_LO (2 * 128 * ASB + 64 * ASB)
#define SM_TOTAL (2 * 128 * ASB + 2 * 64 * ASB)   // 104448

__device__ __forceinline__ uint32_t pack_bf2(__nv_bfloat16 a, __nv_bfloat16 b) {
    return (uint32_t)__bfloat16_as_ushort(a) | ((uint32_t)__bfloat16_as_ushort(b) << 16);
}

__device__ __forceinline__ void mma16816(float* c, const uint32_t* a,
                                         uint32_t b0, uint32_t b1) {
    asm volatile(
        "mma.sync.aligned.m16n8k16.row.col.f32.bf16.bf16.f32 "
        "{%0,%1,%2,%3}, {%4,%5,%6,%7}, {%8,%9}, {%0,%1,%2,%3};"
        : "+f"(c[0]), "+f"(c[1]), "+f"(c[2]), "+f"(c[3])
        : "r"(a[0]), "r"(a[1]), "r"(a[2]), "r"(a[3]), "r"(b0), "r"(b1));
}

__global__ void __launch_bounds__(256, 2) k_gemm_mma(const float* __restrict__ x,
                                                     const float* __restrict__ W) {
    extern __shared__ char smem[];
    int tid = threadIdx.x;
    int base = blockIdx.x * 128;

    for (int i = tid; i < 128 * 32; i += 256) {
        int row = i >> 5, kq = i & 31;
        int gn = base + row;
        float4 v = make_float4(0.f, 0.f, 0.f, 0.f);
        if (gn < NN) v = ((const float4*)x)[(size_t)gn * 32 + kq];
        float e[4] = {v.x, v.y, v.z, v.w};
        __nv_bfloat16 h[4], l[4];
        #pragma unroll
        for (int j = 0; j < 4; j++) {
            h[j] = __float2bfloat16(e[j]);
            l[j] = __float2bfloat16(e[j] - __bfloat162float(h[j]));
        }
        uint32_t off = row * ASB + kq * 8;
        *(ull*)(smem + SM_A_HI + off) =
            (ull)pack_bf2(h[0], h[1]) | ((ull)pack_bf2(h[2], h[3]) << 32);
        *(ull*)(smem + SM_A_LO + off) =
            (ull)pack_bf2(l[0], l[1]) | ((ull)pack_bf2(l[2], l[3]) << 32);
    }
    for (int i = tid; i < 64 * 32; i += 256) {
        int row = i >> 5, kq = i & 31;
        float4 v = ((const float4*)W)[row * 32 + kq];
        float e[4] = {v.x, v.y, v.z, v.w};
        __nv_bfloat16 h[4], l[4];
        #pragma unroll
        for (int j = 0; j < 4; j++) {
            h[j] = __float2bfloat16(e[j]);
            l[j] = __float2bfloat16(e[j] - __bfloat162float(h[j]));
        }
        uint32_t off = row * ASB + kq * 8;
        *(ull*)(smem + SM_B_HI + off) =
            (ull)pack_bf2(h[0], h[1]) | ((ull)pack_bf2(h[2], h[3]) << 32);
        *(ull*)(smem + SM_B_LO + off) =
            (ull)pack_bf2(l[0], l[1]) | ((ull)pack_bf2(l[2], l[3]) << 32);
    }
    __syncthreads();

    int w  = tid >> 5;
    int l  = tid & 31;
    int g  = l >> 2;
    int tg = l & 3;
    int ar0 = w * 16 + g;

    float c[8][4];
    #pragma unroll
    for (int nt = 0; nt < 8; nt++)
        #pragma unroll
        for (int j = 0; j < 4; j++) c[nt][j] = 0.f;

    #pragma unroll
    for (int ks = 0; ks < 8; ks++) {
        int k0 = ks * 16;
        uint32_t aoff = ar0 * ASB + (k0 + tg * 2) * 2;
        uint32_t ah[4], al[4];
        ah[0] = *(const uint32_t*)(smem + SM_A_HI + aoff);
        ah[1] = *(const uint32_t*)(smem + SM_A_HI + aoff + 8 * ASB);
        ah[2] = *(const uint32_t*)(smem + SM_A_HI + aoff + 16);
        ah[3] = *(const uint32_t*)(smem + SM_A_HI + aoff + 8 * ASB + 16);
        al[0] = *(const uint32_t*)(smem + SM_A_LO + aoff);
        al[1] = *(const uint32_t*)(smem + SM_A_LO + aoff + 8 * ASB);
        al[2] = *(const uint32_t*)(smem + SM_A_LO + aoff + 16);
        al[3] = *(const uint32_t*)(smem + SM_A_LO + aoff + 8 * ASB + 16);
        #pragma unroll
        for (int nt = 0; nt < 8; nt++) {
            uint32_t boff = (nt * 8 + g) * ASB + (k0 + tg * 2) * 2;
            uint32_t bh0 = *(const uint32_t*)(smem + SM_B_HI + boff);
            uint32_t bh1 = *(const uint32_t*)(smem + SM_B_HI + boff + 16);
            uint32_t bl0 = *(const uint32_t*)(smem + SM_B_LO + boff);
            uint32_t bl1 = *(const uint32_t*)(smem + SM_B_LO + boff + 16);
            mma16816(c[nt], ah, bh0, bh1);
            mma16816(c[nt], al, bh0, bh1);
            mma16816(c[nt], ah, bl0, bl1);
        }
    }

    float2* yp = (float2*)g_y4;
    int gn0 = base + ar0;
    int gn1 = gn0 + 8;
    #pragma unroll
    for (int nt = 0; nt < 8; nt++) {
        if (gn0 < NN) yp[(size_t)gn0 * 32 + nt * 4 + tg] = make_float2(c[nt][0], c[nt][1]);
        if (gn1 < NN) yp[(size_t)gn1 * 32 + nt * 4 + tg] = make_float2(c[nt][2], c[nt][3]);
    }
}

// ---------------- gather + epilogue ----------------
// Post-scatter, g_off[v] = inclusive offset: jb = v?g_off[v-1]:0, je = g_off[v].
// Re-zeroes g_cnt and g_flags for the next graph replay.
__global__ void __launch_bounds__(256) k_out(const float* __restrict__ bn,
                                             float* __restrict__ out) {
    int tid = threadIdx.x;
    int gt = blockIdx.x * 256 + tid;
    if (gt < NN) g_cnt[gt] = 0;
    if (blockIdx.x == 0 && tid < NBLK) g_flags[tid] = 0;

    int l  = tid & 15;
    int nl = tid >> 4;
    int v  = blockIdx.x * 16 + nl;     // 6250 * 16 == 100000

    float4 acc = g_y4[(size_t)v * 16 + l];   // self term

    int jb = v ? g_off[v - 1] : 0;
    int je = g_off[v];
    int j = jb;
    for (; j + 4 <= je; j += 4) {
        int s0 = g_srcs[j + 0];
        int s1 = g_srcs[j + 1];
        int s2 = g_srcs[j + 2];
        int s3 = g_srcs[j + 3];
        float4 t0 = g_y4[(size_t)s0 * 16 + l];
        float4 t1 = g_y4[(size_t)s1 * 16 + l];
        float4 t2 = g_y4[(size_t)s2 * 16 + l];
        float4 t3 = g_y4[(size_t)s3 * 16 + l];
        acc.x += t0.x + t1.x + t2.x + t3.x;
        acc.y += t0.y + t1.y + t2.y + t3.y;
        acc.z += t0.z + t1.z + t2.z + t3.z;
        acc.w += t0.w + t1.w + t2.w + t3.w;
    }
    for (; j < je; j++) {
        int s = g_srcs[j];
        float4 t = g_y4[(size_t)s * 16 + l];
        acc.x += t.x; acc.y += t.y; acc.z += t.z; acc.w += t.w;
    }

    float sc = 1.0f / (float)(je - jb + 1);
    float4 bb = ((const float4*)bn)[l];
    float4 o;
    o.x = acc.x * sc + bb.x;
    o.y = acc.y * sc + bb.y;
    o.z = acc.z * sc + bb.z;
    o.w = acc.w * sc + bb.w;
    ((float4*)out)[(size_t)v * 16 + l] = o;
}

extern "C" void kernel_launch(void* const* d_in, const int* in_sizes, int n_in,
                              void* d_out, int out_size) {
    const float* x    = (const float*)d_in[0];
    const int*   esrc = (const int*)d_in[1];
    const int*   edst = (const int*)d_in[2];
    const float* W    = (const float*)d_in[3];
    const float* bn   = (const float*)d_in[4];
    float* out = (float*)d_out;

    static cudaStream_t s1 = nullptr;
    static cudaEvent_t ev_root = nullptr, ev_gemm = nullptr;
    if (!s1) {
        cudaStreamCreateWithFlags(&s1, cudaStreamNonBlocking);
        cudaEventCreateWithFlags(&ev_root, cudaEventDisableTiming);
        cudaEventCreateWithFlags(&ev_gemm, cudaEventDisableTiming);
        cudaFuncSetAttribute(k_gemm_mma, cudaFuncAttributeMaxDynamicSharedMemorySize, SM_TOTAL);
    }

    // fork: GEMM on side stream, CSR build on main stream
    cudaEventRecord(ev_root, 0);
    cudaStreamWaitEvent(s1, ev_root, 0);
    k_gemm_mma<<<(NN + 127) / 128, 256, SM_TOTAL, s1>>>(x, W);
    cudaEventRecord(ev_gemm, s1);

    k_count<<<(NE + 255) / 256, 256>>>(edst);
    k_scan<<<NBLK, 1024>>>();
    k_scatter<<<(NE + 255) / 256, 256>>>(esrc, edst);

    // join: k_out needs both g_y (gemm) and CSR
    cudaStreamWaitEvent(0, ev_gemm, 0);
    k_out<<<NN / 16, 256>>>(bn, out);
}